// round 13
// baseline (speedup 1.0000x reference)
#include <cuda_runtime.h>
#include <cstdint>

#define E_    12
#define D_    768
#define KDIM  1536
#define NE    24
#define ROWS  32            // rows per tile; each CTA does 2 tiles (64 rows)
#define CROWS 64
#define KC    128           // K chunk
#define NCH   12            // chunks per tile
#define GSTR  132           // G row stride (floats): 528B == 16 mod 128 -> conflict-free
#define WSTR  132
#define GBUF  (ROWS * GSTR) // 4224 floats
#define WBUF  (NE * WSTR)   // 3168 floats
#define NSTG  (ROWS + NE)   // 56 staging threads

__device__ __forceinline__ void ffma2(unsigned long long &d,
                                      unsigned long long a,
                                      unsigned long long b) {
    asm("fma.rn.f32x2 %0, %1, %2, %0;" : "+l"(d) : "l"(a), "l"(b));
}
__device__ __forceinline__ float2 unpack2(unsigned long long v) {
    float2 r;
    asm("mov.b64 {%0, %1}, %2;" : "=f"(r.x), "=f"(r.y) : "l"(v));
    return r;
}
__device__ __forceinline__ void bulk512(uint32_t dst, const float* src, uint32_t mbar) {
    asm volatile(
        "cp.async.bulk.shared::cluster.global.mbarrier::complete_tx::bytes "
        "[%0], [%1], 512, [%2];"
        :: "r"(dst), "l"(src), "r"(mbar) : "memory");
}
__device__ __forceinline__ void expect_tx(uint32_t mbar, uint32_t bytes) {
    asm volatile("mbarrier.arrive.expect_tx.shared.b64 _, [%0], %1;"
                 :: "r"(mbar), "r"(bytes) : "memory");
}
__device__ __forceinline__ void wait_parity(uint32_t mbar, uint32_t parity) {
    uint32_t done;
    asm volatile(
        "{\n\t.reg .pred p;\n\t"
        "mbarrier.try_wait.parity.acquire.cta.shared::cta.b64 p, [%1], %2;\n\t"
        "selp.b32 %0, 1, 0, p;\n\t}"
        : "=r"(done) : "r"(mbar), "r"(parity) : "memory");
    if (!done) {
        asm volatile(
            "{\n\t.reg .pred P1;\n\t"
            "WL_%=:\n\t"
            "mbarrier.try_wait.parity.acquire.cta.shared::cta.b64 P1, [%0], %1, 0x989680;\n\t"
            "@P1 bra.uni WD_%=;\n\t"
            "bra.uni WL_%=;\n\t"
            "WD_%=:\n\t}"
            :: "r"(mbar), "r"(parity) : "memory");
    }
}

// ── Fused: 2-tile CTA; GEMM(B) overlapped with gather(A); gather(B) in epilogue ──
__global__ void __launch_bounds__(256, 2) gate_fused(
    const float* __restrict__ audio, const float* __restrict__ image,
    const float* __restrict__ Wa,    const float* __restrict__ ba,
    const float* __restrict__ Wi,    const float* __restrict__ bi,
    const float* __restrict__ ga,    const float* __restrict__ gi,
    float* __restrict__ out, int B)
{
    extern __shared__ float sm[];
    float* Gm    = sm;                       // 2 x GBUF (double buffer)
    float* Wm    = sm + 2 * GBUF;            // 2 x WBUF (double buffer)
    float* Ls    = Wm + 2 * WBUF;            // ROWS x NE reduced logits
    float* s_scl = Ls + ROWS * NE;           // [2][ROWS] per-tile (reused)
    int*   s_idx = (int*)(s_scl + 2 * ROWS); // [2][ROWS]
    float* Lp    = Gm;                       // alias: 8 x ROWS x NE partials
    uint32_t mb0 = (uint32_t)__cvta_generic_to_shared(
                       (void*)(s_idx + 2 * ROWS));  // 2 mbarriers (16 B)

    const int tid  = threadIdx.x;
    const int lane = tid & 31;
    const int wid  = tid >> 5;
    const int ksl  = wid;              // warp = K-slice: floats ksl*16..+15 per chunk
    const int rp   = lane >> 2;        // row base (0..7); rows rp+8j, j<4
    const int eg   = lane & 3;         // experts eg*6 .. eg*6+5
    const int row0 = blockIdx.x * CROWS;

    const uint32_t gsm = (uint32_t)__cvta_generic_to_shared(Gm);
    const uint32_t wsm = (uint32_t)__cvta_generic_to_shared(Wm);
    const size_t rowstride = (size_t)E_ * D_;   // 9216

    if (tid == 0) {
        asm volatile("mbarrier.init.shared.b64 [%0], 56;" :: "r"(mb0) : "memory");
        asm volatile("mbarrier.init.shared.b64 [%0], 56;" :: "r"(mb0 + 8) : "memory");
        asm volatile("fence.proxy.async.shared::cta;" ::: "memory");
    }
    __syncthreads();

    // Stage one chunk (global chunk id cc in 0..23)
    auto stage = [&](int cc) {
        const int tile = cc >= NCH;
        const int c    = cc - (tile ? NCH : 0);
        const uint32_t buf  = cc & 1;
        const uint32_t mbar = mb0 + buf * 8;
        if (tid < ROWS) {
            int b = row0 + tile * ROWS + tid; if (b >= B) b = B - 1;
            const float* base = (c < NCH / 2) ? audio : image;
            const int kb = (c < NCH / 2) ? c * KC : c * KC - D_;
            expect_tx(mbar, 512);
            bulk512(gsm + buf * (GBUF * 4) + (uint32_t)(tid * GSTR * 4),
                    base + (size_t)b * rowstride + kb, mbar);
        } else if (tid < NSTG) {
            int e = tid - ROWS;
            const float* ws = (e < E_) ? Wa + (size_t)e * KDIM
                                       : Wi + (size_t)(e - E_) * KDIM;
            expect_tx(mbar, 512);
            bulk512(wsm + buf * (WBUF * 4) + (uint32_t)((tid - ROWS) * WSTR * 4),
                    ws + c * KC, mbar);
        }
    };

    float4 pv[4];   // gather pipeline payload
    float  psc[4];  // gather pipeline scales

    for (int tile = 0; tile < 2; tile++) {
        unsigned long long acc[4][6];
        #pragma unroll
        for (int j = 0; j < 4; j++)
            #pragma unroll
            for (int m = 0; m < 6; m++) acc[j][m] = 0ULL;

        stage(tile * NCH);

        for (int c = 0; c < NCH; c++) {
            const int cc = tile * NCH + c;
            if (c + 1 < NCH) stage(cc + 1);
            wait_parity(mb0 + (cc & 1) * 8, (cc >> 1) & 1);

            const float* gb = Gm + (cc & 1) * GBUF;
            const float* wb = Wm + (cc & 1) * WBUF;
            const int cb = ksl * 16;
            #pragma unroll
            for (int kk = 0; kk < 4; kk++) {
                const int col = cb + kk * 4;
                ulonglong2 g[4];
                #pragma unroll
                for (int j = 0; j < 4; j++)
                    g[j] = *(const ulonglong2*)(gb + (rp + 8 * j) * GSTR + col);
                #pragma unroll
                for (int m = 0; m < 6; m++) {
                    ulonglong2 w = *(const ulonglong2*)(wb + (eg * 6 + m) * WSTR + col);
                    #pragma unroll
                    for (int j = 0; j < 4; j++) {
                        ffma2(acc[j][m], g[j].x, w.x);
                        ffma2(acc[j][m], g[j].y, w.y);
                    }
                }
            }

            if (tile == 1) {
                // ---- interleaved gather of tile A (software-pipelined) ----
                if (c > 0) {
                    const int cp = c - 1;
                    #pragma unroll
                    for (int i = 0; i < 4; i++) {
                        int Q = cp * 1024 + i * 256 + tid;
                        int row = Q / 384, q = Q - row * 384;
                        int b = row0 + row;
                        if (b < B) {
                            float4 t = pv[i];
                            t.x *= psc[i]; t.y *= psc[i]; t.z *= psc[i]; t.w *= psc[i];
                            *(float4*)(out + (size_t)b * KDIM + q * 4) = t;
                        }
                    }
                }
                #pragma unroll
                for (int i = 0; i < 4; i++) {
                    int Q = c * 1024 + i * 256 + tid;
                    int row = Q / 384, q = Q - row * 384;
                    int b = row0 + row; if (b >= B) b = B - 1;
                    if (q < 192) {
                        psc[i] = s_scl[row];
                        pv[i]  = *(const float4*)(audio
                                  + ((size_t)b * E_ + s_idx[row]) * D_ + q * 4);
                    } else {
                        psc[i] = s_scl[ROWS + row];
                        pv[i]  = *(const float4*)(image
                                  + ((size_t)b * E_ + s_idx[ROWS + row]) * D_
                                  + (q - 192) * 4);
                    }
                }
            }
            __syncthreads();   // buffer reads done before restage / Lp alias
        }

        if (tile == 1) {
            // drain last gather-A slice (c = 11)
            #pragma unroll
            for (int i = 0; i < 4; i++) {
                int Q = 11 * 1024 + i * 256 + tid;
                int row = Q / 384, q = Q - row * 384;
                int b = row0 + row;
                if (b < B) {
                    float4 t = pv[i];
                    t.x *= psc[i]; t.y *= psc[i]; t.z *= psc[i]; t.w *= psc[i];
                    *(float4*)(out + (size_t)b * KDIM + q * 4) = t;
                }
            }
        }

        // ---- deposit split-K partials (deterministic order) ----
        #pragma unroll
        for (int j = 0; j < 4; j++)
            #pragma unroll
            for (int m = 0; m < 6; m++) {
                float2 p = unpack2(acc[j][m]);
                Lp[(ksl * ROWS + rp + 8 * j) * NE + eg * 6 + m] = p.x + p.y;
            }
        __syncthreads();

        // ---- reduce 8 K-slices in fixed order: 768 sums, 3/thread ----
        #pragma unroll
        for (int t = 0; t < 3; t++) {
            int idx = tid * 3 + t;
            int r = idx / NE;
            int e = idx - r * NE;
            float s = 0.f;
            #pragma unroll
            for (int k = 0; k < 8; k++) s += Lp[(k * ROWS + r) * NE + e];
            Ls[r * NE + e] = s;
        }
        __syncthreads();

        // ---- gumbel-softmax straight-through (one thread per row) ----
        if (tid < ROWS) {
            int b = row0 + tile * ROWS + tid;
            if (b < B) {
                float* retA = out + (size_t)B * KDIM;
                float* retI = retA + (size_t)B * E_;
                #pragma unroll
                for (int gsel = 0; gsel < 2; gsel++) {
                    const float* bias = gsel ? bi : ba;
                    const float* gum  = gsel ? gi : ga;
                    float* retp       = gsel ? retI : retA;
                    float l[E_];
                    float mx = -1e30f;
                    #pragma unroll
                    for (int e = 0; e < E_; e++) {
                        l[e] = Ls[tid * NE + gsel * E_ + e] + bias[e]
                             + gum[(size_t)b * E_ + e];
                        mx = fmaxf(mx, l[e]);
                    }
                    float s = 0.f;
                    float y[E_];
                    #pragma unroll
                    for (int e = 0; e < E_; e++) { y[e] = expf(l[e] - mx); s += y[e]; }
                    const float inv = 1.0f / s;
                    float ys[E_];
                    int   am = 0;
                    float best = y[0] * inv;
                    ys[0] = best;
                    #pragma unroll
                    for (int e = 1; e < E_; e++) {
                        ys[e] = y[e] * inv;
                        if (ys[e] > best) { best = ys[e]; am = e; }  // first-max
                    }
                    #pragma unroll
                    for (int e = 0; e < E_; e++) {
                        float h = (e == am) ? 1.0f : 0.0f;
                        retp[(size_t)b * E_ + e] = (h - ys[e]) + ys[e];  // exact ref
                    }
                    s_scl[gsel * ROWS + tid] = ((1.0f - ys[am]) + ys[am]) * (1.0f / 12.0f);
                    s_idx[gsel * ROWS + tid] = am;
                }
            }
        }
        __syncthreads();   // scl/idx visible before next tile's gather / epilogue
    }

    // ---- exposed gather of tile B: warp-per-row, 12 independent LDG.128 ----
    #pragma unroll
    for (int k = 0; k < 4; k++) {
        const int rl = wid + 8 * k;            // local row 0..31 (tile B)
        const int b  = row0 + ROWS + rl;
        if (b >= B) continue;
        const float sa = s_scl[rl];
        const float si = s_scl[ROWS + rl];
        const float* ap = audio + ((size_t)b * E_ + s_idx[rl]) * D_;
        const float* ip = image + ((size_t)b * E_ + s_idx[ROWS + rl]) * D_;
        float*       op = out + (size_t)b * KDIM;

        float4 v[12];
        #pragma unroll
        for (int j = 0; j < 6; j++)
            v[j] = *(const float4*)(ap + (lane + 32 * j) * 4);
        #pragma unroll
        for (int j = 0; j < 6; j++)
            v[6 + j] = *(const float4*)(ip + (lane + 32 * j) * 4);
        #pragma unroll
        for (int j = 0; j < 6; j++) {
            float4 t = v[j];
            t.x *= sa; t.y *= sa; t.z *= sa; t.w *= sa;
            *(float4*)(op + (lane + 32 * j) * 4) = t;
        }
        #pragma unroll
        for (int j = 0; j < 6; j++) {
            float4 t = v[6 + j];
            t.x *= si; t.y *= si; t.z *= si; t.w *= si;
            *(float4*)(op + D_ + (lane + 32 * j) * 4) = t;
        }
    }
}

#define SMEM_BYTES (((2 * GBUF + 2 * WBUF + ROWS * NE + 2 * ROWS) * 4) \
                    + (2 * ROWS) * 4 + 16)

extern "C" void kernel_launch(void* const* d_in, const int* in_sizes, int n_in,
                              void* d_out, int out_size) {
    const float* audio = (const float*)d_in[0];
    const float* image = (const float*)d_in[1];
    const float* Wa    = (const float*)d_in[2];
    const float* ba    = (const float*)d_in[3];
    const float* Wi    = (const float*)d_in[4];
    const float* bi    = (const float*)d_in[5];
    const float* ga    = (const float*)d_in[6];
    const float* gi    = (const float*)d_in[7];
    float* out = (float*)d_out;

    const int B = in_sizes[0] / (E_ * D_);     // 16384

    static bool attr_set = false;
    if (!attr_set) {
        cudaFuncSetAttribute(gate_fused,
                             cudaFuncAttributeMaxDynamicSharedMemorySize, SMEM_BYTES);
        attr_set = true;
    }

    const int grid = (B + CROWS - 1) / CROWS;  // 256 -> one wave at 2 CTAs/SM
    gate_fused<<<grid, 256, SMEM_BYTES>>>(audio, image, Wa, ba, Wi, bi,
                                          ga, gi, out, B);
}

// round 14
// speedup vs baseline: 1.0134x; 1.0134x over previous
#include <cuda_runtime.h>
#include <cstdint>

#define E_    12
#define D_    768
#define KDIM  1536
#define NE    24
#define ROWS  32            // rows per tile; each CTA does 2 tiles (64 rows)
#define CROWS 64
#define KC    128           // K chunk
#define NCH   12            // chunks per tile
#define GSTR  132           // G row stride (floats): 528B == 16 mod 128 -> conflict-free
#define WSTR  132
#define GBUF  (ROWS * GSTR) // 4224 floats
#define WBUF  (NE * WSTR)   // 3168 floats
#define NSTG  (ROWS + NE)   // 56 staging threads

__device__ __forceinline__ void ffma2(unsigned long long &d,
                                      unsigned long long a,
                                      unsigned long long b) {
    asm("fma.rn.f32x2 %0, %1, %2, %0;" : "+l"(d) : "l"(a), "l"(b));
}
__device__ __forceinline__ float2 unpack2(unsigned long long v) {
    float2 r;
    asm("mov.b64 {%0, %1}, %2;" : "=f"(r.x), "=f"(r.y) : "l"(v));
    return r;
}
__device__ __forceinline__ void bulk512(uint32_t dst, const float* src, uint32_t mbar) {
    asm volatile(
        "cp.async.bulk.shared::cluster.global.mbarrier::complete_tx::bytes "
        "[%0], [%1], 512, [%2];"
        :: "r"(dst), "l"(src), "r"(mbar) : "memory");
}
__device__ __forceinline__ void expect_tx(uint32_t mbar, uint32_t bytes) {
    asm volatile("mbarrier.arrive.expect_tx.shared.b64 _, [%0], %1;"
                 :: "r"(mbar), "r"(bytes) : "memory");
}
__device__ __forceinline__ void wait_parity(uint32_t mbar, uint32_t parity) {
    uint32_t done;
    asm volatile(
        "{\n\t.reg .pred p;\n\t"
        "mbarrier.try_wait.parity.acquire.cta.shared::cta.b64 p, [%1], %2;\n\t"
        "selp.b32 %0, 1, 0, p;\n\t}"
        : "=r"(done) : "r"(mbar), "r"(parity) : "memory");
    if (!done) {
        asm volatile(
            "{\n\t.reg .pred P1;\n\t"
            "WL_%=:\n\t"
            "mbarrier.try_wait.parity.acquire.cta.shared::cta.b64 P1, [%0], %1, 0x989680;\n\t"
            "@P1 bra.uni WD_%=;\n\t"
            "bra.uni WL_%=;\n\t"
            "WD_%=:\n\t}"
            :: "r"(mbar), "r"(parity) : "memory");
    }
}

// ── Fused: 2-tile CTA; GEMM(B) overlapped with gather(A); gather(B) in epilogue ──
__global__ void __launch_bounds__(256, 2) gate_fused(
    const float* __restrict__ audio, const float* __restrict__ image,
    const float* __restrict__ Wa,    const float* __restrict__ ba,
    const float* __restrict__ Wi,    const float* __restrict__ bi,
    const float* __restrict__ ga,    const float* __restrict__ gi,
    float* __restrict__ out, int B)
{
    extern __shared__ float sm[];
    float* Gm    = sm;                       // 2 x GBUF (double buffer)
    float* Wm    = sm + 2 * GBUF;            // 2 x WBUF (double buffer)
    float* Ls    = Wm + 2 * WBUF;            // ROWS x NE reduced logits
    float* s_scl = Ls + ROWS * NE;           // [2][ROWS] per-tile (reused)
    int*   s_idx = (int*)(s_scl + 2 * ROWS); // [2][ROWS]
    float* Lp    = Gm;                       // alias: 8 x ROWS x NE partials
    uint32_t mb0 = (uint32_t)__cvta_generic_to_shared(
                       (void*)(s_idx + 2 * ROWS));  // 2 mbarriers (16 B)

    const int tid  = threadIdx.x;
    const int lane = tid & 31;
    const int wid  = tid >> 5;
    const int ksl  = wid;              // warp = K-slice: floats ksl*16..+15 per chunk
    const int rp   = lane >> 2;        // row base (0..7); rows rp+8j, j<4
    const int eg   = lane & 3;         // experts eg*6 .. eg*6+5
    const int row0 = blockIdx.x * CROWS;

    const uint32_t gsm = (uint32_t)__cvta_generic_to_shared(Gm);
    const uint32_t wsm = (uint32_t)__cvta_generic_to_shared(Wm);
    const size_t rowstride = (size_t)E_ * D_;   // 9216

    if (tid == 0) {
        asm volatile("mbarrier.init.shared.b64 [%0], 56;" :: "r"(mb0) : "memory");
        asm volatile("mbarrier.init.shared.b64 [%0], 56;" :: "r"(mb0 + 8) : "memory");
        asm volatile("fence.proxy.async.shared::cta;" ::: "memory");
    }
    __syncthreads();

    // Stage one chunk (global chunk id cc in 0..23)
    auto stage = [&](int cc) {
        const int tile = cc >= NCH;
        const int c    = cc - (tile ? NCH : 0);
        const uint32_t buf  = cc & 1;
        const uint32_t mbar = mb0 + buf * 8;
        if (tid < ROWS) {
            int b = row0 + tile * ROWS + tid; if (b >= B) b = B - 1;
            const float* base = (c < NCH / 2) ? audio : image;
            const int kb = (c < NCH / 2) ? c * KC : c * KC - D_;
            expect_tx(mbar, 512);
            bulk512(gsm + buf * (GBUF * 4) + (uint32_t)(tid * GSTR * 4),
                    base + (size_t)b * rowstride + kb, mbar);
        } else if (tid < NSTG) {
            int e = tid - ROWS;
            const float* ws = (e < E_) ? Wa + (size_t)e * KDIM
                                       : Wi + (size_t)(e - E_) * KDIM;
            expect_tx(mbar, 512);
            bulk512(wsm + buf * (WBUF * 4) + (uint32_t)((tid - ROWS) * WSTR * 4),
                    ws + c * KC, mbar);
        }
    };

    float4 pv[4];   // gather pipeline payload
    float  psc[4];  // gather pipeline scales

    for (int tile = 0; tile < 2; tile++) {
        unsigned long long acc[4][6];
        #pragma unroll
        for (int j = 0; j < 4; j++)
            #pragma unroll
            for (int m = 0; m < 6; m++) acc[j][m] = 0ULL;

        stage(tile * NCH);

        for (int c = 0; c < NCH; c++) {
            const int cc = tile * NCH + c;
            if (c + 1 < NCH) stage(cc + 1);
            wait_parity(mb0 + (cc & 1) * 8, (cc >> 1) & 1);

            const float* gb = Gm + (cc & 1) * GBUF;
            const float* wb = Wm + (cc & 1) * WBUF;
            const int cb = ksl * 16;
            #pragma unroll
            for (int kk = 0; kk < 4; kk++) {
                const int col = cb + kk * 4;
                ulonglong2 g[4];
                #pragma unroll
                for (int j = 0; j < 4; j++)
                    g[j] = *(const ulonglong2*)(gb + (rp + 8 * j) * GSTR + col);
                #pragma unroll
                for (int m = 0; m < 6; m++) {
                    ulonglong2 w = *(const ulonglong2*)(wb + (eg * 6 + m) * WSTR + col);
                    #pragma unroll
                    for (int j = 0; j < 4; j++) {
                        ffma2(acc[j][m], g[j].x, w.x);
                        ffma2(acc[j][m], g[j].y, w.y);
                    }
                }
            }

            if (tile == 1) {
                // ---- interleaved gather of tile A (software-pipelined) ----
                if (c > 0) {
                    const int cp = c - 1;
                    #pragma unroll
                    for (int i = 0; i < 4; i++) {
                        int Q = cp * 1024 + i * 256 + tid;
                        int row = Q / 384, q = Q - row * 384;
                        int b = row0 + row;
                        if (b < B) {
                            float4 t = pv[i];
                            t.x *= psc[i]; t.y *= psc[i]; t.z *= psc[i]; t.w *= psc[i];
                            *(float4*)(out + (size_t)b * KDIM + q * 4) = t;
                        }
                    }
                }
                #pragma unroll
                for (int i = 0; i < 4; i++) {
                    int Q = c * 1024 + i * 256 + tid;
                    int row = Q / 384, q = Q - row * 384;
                    int b = row0 + row; if (b >= B) b = B - 1;
                    if (q < 192) {
                        psc[i] = s_scl[row];
                        pv[i]  = *(const float4*)(audio
                                  + ((size_t)b * E_ + s_idx[row]) * D_ + q * 4);
                    } else {
                        psc[i] = s_scl[ROWS + row];
                        pv[i]  = *(const float4*)(image
                                  + ((size_t)b * E_ + s_idx[ROWS + row]) * D_
                                  + (q - 192) * 4);
                    }
                }
            }
            __syncthreads();   // buffer reads done before restage / Lp alias
        }

        if (tile == 1) {
            // drain last gather-A slice (c = 11)
            #pragma unroll
            for (int i = 0; i < 4; i++) {
                int Q = 11 * 1024 + i * 256 + tid;
                int row = Q / 384, q = Q - row * 384;
                int b = row0 + row;
                if (b < B) {
                    float4 t = pv[i];
                    t.x *= psc[i]; t.y *= psc[i]; t.z *= psc[i]; t.w *= psc[i];
                    *(float4*)(out + (size_t)b * KDIM + q * 4) = t;
                }
            }
        }

        // ---- deposit split-K partials (deterministic order) ----
        #pragma unroll
        for (int j = 0; j < 4; j++)
            #pragma unroll
            for (int m = 0; m < 6; m++) {
                float2 p = unpack2(acc[j][m]);
                Lp[(ksl * ROWS + rp + 8 * j) * NE + eg * 6 + m] = p.x + p.y;
            }
        __syncthreads();

        // ---- reduce 8 K-slices in fixed order: 768 sums, 3/thread ----
        #pragma unroll
        for (int t = 0; t < 3; t++) {
            int idx = tid * 3 + t;
            int r = idx / NE;
            int e = idx - r * NE;
            float s = 0.f;
            #pragma unroll
            for (int k = 0; k < 8; k++) s += Lp[(k * ROWS + r) * NE + e];
            Ls[r * NE + e] = s;
        }
        __syncthreads();

        // ---- gumbel-softmax straight-through (one thread per row) ----
        if (tid < ROWS) {
            int b = row0 + tile * ROWS + tid;
            if (b < B) {
                float* retA = out + (size_t)B * KDIM;
                float* retI = retA + (size_t)B * E_;
                #pragma unroll
                for (int gsel = 0; gsel < 2; gsel++) {
                    const float* bias = gsel ? bi : ba;
                    const float* gum  = gsel ? gi : ga;
                    float* retp       = gsel ? retI : retA;
                    float l[E_];
                    float mx = -1e30f;
                    #pragma unroll
                    for (int e = 0; e < E_; e++) {
                        l[e] = Ls[tid * NE + gsel * E_ + e] + bias[e]
                             + gum[(size_t)b * E_ + e];
                        mx = fmaxf(mx, l[e]);
                    }
                    float s = 0.f;
                    float y[E_];
                    #pragma unroll
                    for (int e = 0; e < E_; e++) { y[e] = expf(l[e] - mx); s += y[e]; }
                    const float inv = 1.0f / s;
                    float ys[E_];
                    int   am = 0;
                    float best = y[0] * inv;
                    ys[0] = best;
                    #pragma unroll
                    for (int e = 1; e < E_; e++) {
                        ys[e] = y[e] * inv;
                        if (ys[e] > best) { best = ys[e]; am = e; }  // first-max
                    }
                    #pragma unroll
                    for (int e = 0; e < E_; e++) {
                        float h = (e == am) ? 1.0f : 0.0f;
                        retp[(size_t)b * E_ + e] = (h - ys[e]) + ys[e];  // exact ref
                    }
                    s_scl[gsel * ROWS + tid] = ((1.0f - ys[am]) + ys[am]) * (1.0f / 12.0f);
                    s_idx[gsel * ROWS + tid] = am;
                }
            }
        }
        __syncthreads();   // scl/idx visible before next tile's gather / epilogue
    }

    // ---- exposed gather of tile B: warp-per-row, 12 independent LDG.128 ----
    #pragma unroll
    for (int k = 0; k < 4; k++) {
        const int rl = wid + 8 * k;            // local row 0..31 (tile B)
        const int b  = row0 + ROWS + rl;
        if (b >= B) continue;
        const float sa = s_scl[rl];
        const float si = s_scl[ROWS + rl];
        const float* ap = audio + ((size_t)b * E_ + s_idx[rl]) * D_;
        const float* ip = image + ((size_t)b * E_ + s_idx[ROWS + rl]) * D_;
        float*       op = out + (size_t)b * KDIM;

        float4 v[12];
        #pragma unroll
        for (int j = 0; j < 6; j++)
            v[j] = *(const float4*)(ap + (lane + 32 * j) * 4);
        #pragma unroll
        for (int j = 0; j < 6; j++)
            v[6 + j] = *(const float4*)(ip + (lane + 32 * j) * 4);
        #pragma unroll
        for (int j = 0; j < 6; j++) {
            float4 t = v[j];
            t.x *= sa; t.y *= sa; t.z *= sa; t.w *= sa;
            *(float4*)(op + (lane + 32 * j) * 4) = t;
        }
        #pragma unroll
        for (int j = 0; j < 6; j++) {
            float4 t = v[6 + j];
            t.x *= si; t.y *= si; t.z *= si; t.w *= si;
            *(float4*)(op + D_ + (lane + 32 * j) * 4) = t;
        }
    }
}

#define SMEM_BYTES (((2 * GBUF + 2 * WBUF + ROWS * NE + 2 * ROWS) * 4) \
                    + (2 * ROWS) * 4 + 16)

extern "C" void kernel_launch(void* const* d_in, const int* in_sizes, int n_in,
                              void* d_out, int out_size) {
    const float* audio = (const float*)d_in[0];
    const float* image = (const float*)d_in[1];
    const float* Wa    = (const float*)d_in[2];
    const float* ba    = (const float*)d_in[3];
    const float* Wi    = (const float*)d_in[4];
    const float* bi    = (const float*)d_in[5];
    const float* ga    = (const float*)d_in[6];
    const float* gi    = (const float*)d_in[7];
    float* out = (float*)d_out;

    const int B = in_sizes[0] / (E_ * D_);     // 16384

    static bool attr_set = false;
    if (!attr_set) {
        cudaFuncSetAttribute(gate_fused,
                             cudaFuncAttributeMaxDynamicSharedMemorySize, SMEM_BYTES);
        attr_set = true;
    }

    const int grid = (B + CROWS - 1) / CROWS;  // 256 -> one wave at 2 CTAs/SM
    gate_fused<<<grid, 256, SMEM_BYTES>>>(audio, image, Wa, ba, Wi, bi,
                                          ga, gi, out, B);
}

// round 16
// speedup vs baseline: 1.1083x; 1.0936x over previous
#include <cuda_runtime.h>
#include <cstdint>

#define E_    12
#define D_    768
#define KDIM  1536
#define NE    24
#define ROWS  64            // batch rows per CTA: grid 256 -> single wave @ 2/SM
#define KC    128           // K chunk
#define NCH   12            // KDIM / KC
#define GSTR  132           // G row stride (floats): 528B == 16 mod 128 -> conflict-free
#define WSTR  132           // W chunk row stride
#define GBUF  (ROWS * GSTR) // 8448 floats
#define WBUF  (NE * WSTR)   // 3168 floats
#define NSTG  (ROWS + NE)   // 88 staging threads

__device__ __forceinline__ void ffma2(unsigned long long &d,
                                      unsigned long long a,
                                      unsigned long long b) {
    asm("fma.rn.f32x2 %0, %1, %2, %0;" : "+l"(d) : "l"(a), "l"(b));
}
__device__ __forceinline__ float2 unpack2(unsigned long long v) {
    float2 r;
    asm("mov.b64 {%0, %1}, %2;" : "=f"(r.x), "=f"(r.y) : "l"(v));
    return r;
}
__device__ __forceinline__ void bulk512(uint32_t dst, const float* src, uint32_t mbar) {
    asm volatile(
        "cp.async.bulk.shared::cluster.global.mbarrier::complete_tx::bytes "
        "[%0], [%1], 512, [%2];"
        :: "r"(dst), "l"(src), "r"(mbar) : "memory");
}
__device__ __forceinline__ void expect_tx(uint32_t mbar, uint32_t bytes) {
    asm volatile("mbarrier.arrive.expect_tx.shared.b64 _, [%0], %1;"
                 :: "r"(mbar), "r"(bytes) : "memory");
}
__device__ __forceinline__ void wait_parity(uint32_t mbar, uint32_t parity) {
    uint32_t done;
    asm volatile(
        "{\n\t.reg .pred p;\n\t"
        "mbarrier.try_wait.parity.acquire.cta.shared::cta.b64 p, [%1], %2;\n\t"
        "selp.b32 %0, 1, 0, p;\n\t}"
        : "=r"(done) : "r"(mbar), "r"(parity) : "memory");
    if (!done) {
        asm volatile(
            "{\n\t.reg .pred P1;\n\t"
            "WL_%=:\n\t"
            "mbarrier.try_wait.parity.acquire.cta.shared::cta.b64 P1, [%0], %1, 0x989680;\n\t"
            "@P1 bra.uni WD_%=;\n\t"
            "bra.uni WL_%=;\n\t"
            "WD_%=:\n\t}"
            :: "r"(mbar), "r"(parity) : "memory");
    }
}

// ── Fused: bulk-async pipelined logits GEMM (4x6 tile) + softmax-ST + gather ──
__global__ void __launch_bounds__(256, 2) gate_fused(
    const float* __restrict__ audio, const float* __restrict__ image,
    const float* __restrict__ Wa,    const float* __restrict__ ba,
    const float* __restrict__ Wi,    const float* __restrict__ bi,
    const float* __restrict__ ga,    const float* __restrict__ gi,
    float* __restrict__ out, int B)
{
    extern __shared__ float sm[];
    float* Gm    = sm;                       // 2 x GBUF (double buffer)
    float* Wm    = sm + 2 * GBUF;            // 2 x WBUF (double buffer)
    float* Ls    = Wm + 2 * WBUF;            // ROWS x NE reduced logits
    float* s_scl = Ls + ROWS * NE;           // [2][ROWS]
    int*   s_idx = (int*)(s_scl + 2 * ROWS); // [2][ROWS]
    float* Lp    = Gm;                       // alias: 4 x ROWS x NE partials
    uint32_t mb0 = (uint32_t)__cvta_generic_to_shared(
                       (void*)(s_idx + 2 * ROWS));  // 2 mbarriers

    const int tid  = threadIdx.x;
    const int lane = tid & 31;
    const int wid  = tid >> 5;
    const int ksl  = wid & 3;          // K-slice: floats ksl*32 .. +31 of each chunk
    const int rg   = wid >> 2;         // row group (0..1) of 32 rows
    const int rp   = lane >> 2;        // row base within group (0..7)
    const int eg   = lane & 3;         // expert group: experts eg*6 .. eg*6+5
    const int rb   = rg * 32 + rp;     // rows rb, rb+8, rb+16, rb+24
    const int row0 = blockIdx.x * ROWS;

    const uint32_t gsm = (uint32_t)__cvta_generic_to_shared(Gm);
    const uint32_t wsm = (uint32_t)__cvta_generic_to_shared(Wm);
    const size_t rowstride = (size_t)E_ * D_;   // 9216

    if (tid == 0) {
        asm volatile("mbarrier.init.shared.b64 [%0], 88;" :: "r"(mb0) : "memory");
        asm volatile("mbarrier.init.shared.b64 [%0], 88;" :: "r"(mb0 + 8) : "memory");
        asm volatile("fence.proxy.async.shared::cta;" ::: "memory");
    }
    __syncthreads();

    // Per-thread staging role: tid<64 -> G row, 64<=tid<88 -> W row
    const float* gsrc_a = nullptr;
    const float* gsrc_i = nullptr;
    const float* wsrc   = nullptr;
    uint32_t     dG = 0, dW = 0;
    if (tid < ROWS) {
        int b = row0 + tid; if (b >= B) b = B - 1;
        gsrc_a = audio + (size_t)b * rowstride;
        gsrc_i = image + (size_t)b * rowstride;
        dG = gsm + (uint32_t)(tid * GSTR * 4);
    } else if (tid < NSTG) {
        int e = tid - ROWS;
        wsrc = (e < E_) ? Wa + (size_t)e * KDIM : Wi + (size_t)(e - E_) * KDIM;
        dW = wsm + (uint32_t)((tid - ROWS) * WSTR * 4);
    }

    auto stage = [&](int c) {
        const uint32_t buf  = c & 1;
        const uint32_t mbar = mb0 + buf * 8;
        if (tid < ROWS) {
            const float* src = (c < NCH / 2) ? (gsrc_a + c * KC)
                                             : (gsrc_i + c * KC - D_);
            expect_tx(mbar, 512);
            bulk512(dG + buf * (GBUF * 4), src, mbar);
        } else if (tid < NSTG) {
            expect_tx(mbar, 512);
            bulk512(dW + buf * (WBUF * 4), wsrc + c * KC, mbar);
        }
    };

    unsigned long long acc[4][6];
    #pragma unroll
    for (int j = 0; j < 4; j++)
        #pragma unroll
        for (int m = 0; m < 6; m++) acc[j][m] = 0ULL;

    stage(0);

    for (int c = 0; c < NCH; c++) {
        if (c + 1 < NCH) stage(c + 1);          // writes buffer freed at prev-iter barrier
        wait_parity(mb0 + (c & 1) * 8, (c >> 1) & 1);

        const float* gb = Gm + (c & 1) * GBUF;
        const float* wb = Wm + (c & 1) * WBUF;
        const int cb = ksl * 32;
        #pragma unroll
        for (int kk = 0; kk < 8; kk++) {
            const int col = cb + kk * 4;
            ulonglong2 g[4];
            #pragma unroll
            for (int j = 0; j < 4; j++)
                g[j] = *(const ulonglong2*)(gb + (rb + 8 * j) * GSTR + col);
            #pragma unroll
            for (int m = 0; m < 6; m++) {
                ulonglong2 w = *(const ulonglong2*)(wb + (eg * 6 + m) * WSTR + col);
                #pragma unroll
                for (int j = 0; j < 4; j++) {
                    ffma2(acc[j][m], g[j].x, w.x);
                    ffma2(acc[j][m], g[j].y, w.y);
                }
            }
        }
        __syncthreads();   // all reads of this buffer done before restage / Lp alias
    }

    // Deposit split-K partials (deterministic order)
    #pragma unroll
    for (int j = 0; j < 4; j++)
        #pragma unroll
        for (int m = 0; m < 6; m++) {
            float2 p = unpack2(acc[j][m]);
            Lp[(ksl * ROWS + rb + 8 * j) * NE + eg * 6 + m] = p.x + p.y;
        }
    __syncthreads();

    // Reduce 4 K-slices in fixed order: 1536 sums, 6/thread
    #pragma unroll
    for (int t = 0; t < 6; t++) {
        int idx = tid * 6 + t;
        int r = idx / NE;
        int e = idx - r * NE;
        float s = 0.f;
        #pragma unroll
        for (int k = 0; k < 4; k++) s += Lp[(k * ROWS + r) * NE + e];
        Ls[r * NE + e] = s;
    }
    __syncthreads();

    // Gumbel-softmax straight-through (one thread per row)
    if (tid < ROWS) {
        int b = row0 + tid;
        if (b < B) {
            float* retA = out + (size_t)B * KDIM;
            float* retI = retA + (size_t)B * E_;
            #pragma unroll
            for (int gsel = 0; gsel < 2; gsel++) {
                const float* bias = gsel ? bi : ba;
                const float* gum  = gsel ? gi : ga;
                float* retp       = gsel ? retI : retA;
                float l[E_];
                float mx = -1e30f;
                #pragma unroll
                for (int e = 0; e < E_; e++) {
                    l[e] = Ls[tid * NE + gsel * E_ + e] + bias[e]
                         + gum[(size_t)b * E_ + e];
                    mx = fmaxf(mx, l[e]);
                }
                float s = 0.f;
                float y[E_];
                #pragma unroll
                for (int e = 0; e < E_; e++) { y[e] = expf(l[e] - mx); s += y[e]; }
                const float inv = 1.0f / s;
                float ys[E_];
                int   am = 0;
                float best = y[0] * inv;
                ys[0] = best;
                #pragma unroll
                for (int e = 1; e < E_; e++) {
                    ys[e] = y[e] * inv;
                    if (ys[e] > best) { best = ys[e]; am = e; }  // first-max (jnp.argmax)
                }
                #pragma unroll
                for (int e = 0; e < E_; e++) {
                    float h = (e == am) ? 1.0f : 0.0f;
                    retp[(size_t)b * E_ + e] = (h - ys[e]) + ys[e];  // exact ref arithmetic
                }
                s_scl[gsel * ROWS + tid] = ((1.0f - ys[am]) + ys[am]) * (1.0f / 12.0f);
                s_idx[gsel * ROWS + tid] = am;
            }
        }
    }
    __syncthreads();

    // ---- gather: warp per row, 12 independent LDG.128 per lane (acc regs dead) ----
    #pragma unroll
    for (int k = 0; k < ROWS / 8; k++) {
        const int rl = wid + 8 * k;        // local row 0..63
        const int b  = row0 + rl;
        if (b >= B) continue;
        const float sa = s_scl[rl];
        const float si = s_scl[ROWS + rl];
        const float* ap = audio + ((size_t)b * E_ + s_idx[rl]) * D_;
        const float* ip = image + ((size_t)b * E_ + s_idx[ROWS + rl]) * D_;
        float*       op = out + (size_t)b * KDIM;

        float4 v[12];
        #pragma unroll
        for (int j = 0; j < 6; j++)
            v[j] = *(const float4*)(ap + (lane + 32 * j) * 4);
        #pragma unroll
        for (int j = 0; j < 6; j++)
            v[6 + j] = *(const float4*)(ip + (lane + 32 * j) * 4);

        #pragma unroll
        for (int j = 0; j < 6; j++) {
            float4 t = v[j];
            t.x *= sa; t.y *= sa; t.z *= sa; t.w *= sa;
            *(float4*)(op + (lane + 32 * j) * 4) = t;
        }
        #pragma unroll
        for (int j = 0; j < 6; j++) {
            float4 t = v[6 + j];
            t.x *= si; t.y *= si; t.z *= si; t.w *= si;
            *(float4*)(op + D_ + (lane + 32 * j) * 4) = t;
        }
    }
}

#define SMEM_BYTES (((2 * GBUF + 2 * WBUF + ROWS * NE + 2 * ROWS) * 4) \
                    + (2 * ROWS) * 4 + 16)   // ~100.2 KB

extern "C" void kernel_launch(void* const* d_in, const int* in_sizes, int n_in,
                              void* d_out, int out_size) {
    const float* audio = (const float*)d_in[0];
    const float* image = (const float*)d_in[1];
    const float* Wa    = (const float*)d_in[2];
    const float* ba    = (const float*)d_in[3];
    const float* Wi    = (const float*)d_in[4];
    const float* bi    = (const float*)d_in[5];
    const float* ga    = (const float*)d_in[6];
    const float* gi    = (const float*)d_in[7];
    float* out = (float*)d_out;

    const int B = in_sizes[0] / (E_ * D_);     // 16384

    static bool attr_set = false;
    if (!attr_set) {
        cudaFuncSetAttribute(gate_fused,
                             cudaFuncAttributeMaxDynamicSharedMemorySize, SMEM_BYTES);
        attr_set = true;
    }

    const int grid = (B + ROWS - 1) / ROWS;    // 256 -> one wave at 2 CTAs/SM
    gate_fused<<<grid, 256, SMEM_BYTES>>>(audio, image, Wa, ba, Wi, bi,
                                          ga, gi, out, B);
}